// round 3
// baseline (speedup 1.0000x reference)
#include <cuda_runtime.h>

typedef unsigned long long ull;

// Repacked twiddles: [stage 0..9][j 0..3][t 0..127] float4, 80KB total.
__device__ float4 g_twp[10 * 4 * 128];

// ---------------- packed f32x2 helpers (Blackwell) ----------------
__device__ __forceinline__ ull bc2(float f) {
    ull r; asm("mov.b64 %0, {%1, %1};" : "=l"(r) : "f"(f)); return r;
}
__device__ __forceinline__ ull pk2(float a, float b) {
    ull r; asm("mov.b64 %0, {%1, %2};" : "=l"(r) : "f"(a), "f"(b)); return r;
}
__device__ __forceinline__ float2 up2(ull u) {
    float2 v; asm("mov.b64 {%0, %1}, %2;" : "=f"(v.x), "=f"(v.y) : "l"(u)); return v;
}
__device__ __forceinline__ ull mul2(ull a, ull b) {
    ull r; asm("mul.rn.f32x2 %0, %1, %2;" : "=l"(r) : "l"(a), "l"(b)); return r;
}
__device__ __forceinline__ ull fma2(ull a, ull b, ull c) {
    ull r; asm("fma.rn.f32x2 %0, %1, %2, %3;" : "=l"(r) : "l"(a), "l"(b), "l"(c)); return r;
}

// ---------------- twiddle repack kernel ----------------
// Original twiddle layout per stage: [512][2][2] floats (q, i, j).
// q for element pair (pL, pL+s): q = ((pL >> (ls+1)) << ls) | (pL & (s-1)).
__global__ void butterfly_prep(const float* __restrict__ tw) {
    int id = blockIdx.x * blockDim.x + threadIdx.x;   // 0..5119
    if (id >= 10 * 4 * 128) return;
    int t  = id & 127;
    int j  = (id >> 7) & 3;
    int ls = id >> 9;
    int s  = 1 << ls;
    const float* st = tw + ls * 2048;                 // stage base
    float4 o;
    if (ls < 3) {
        // phase A: intra-thread, ownership p = 8t + e
        int eL = ((j >> ls) << (ls + 1)) | (j & (s - 1));
        int pL = 8 * t + eL;
        int q  = ((pL >> (ls + 1)) << ls) | (pL & (s - 1));
        o = make_float4(st[q*4+0], st[q*4+1], st[q*4+2], st[q*4+3]);
    } else if (ls < 7) {
        // phase B: shfl stages; thread role i = bit (ls-3) of t
        int i = (t >> (ls - 3)) & 1;
        float v[4];
        #pragma unroll
        for (int m = 0; m < 2; m++) {
            int e = 2 * j + m;
            int p = 8 * t + e;
            int q = ((p >> (ls + 1)) << ls) | (p & (s - 1));
            if (i == 0) { v[2*m] = st[q*4+0]; v[2*m+1] = st[q*4+1]; }  // out = t00*own + t01*other
            else        { v[2*m] = st[q*4+3]; v[2*m+1] = st[q*4+2]; }  // out = t11*own + t10*other
        }
        o = make_float4(v[0], v[1], v[2], v[3]);
    } else {
        // phase C: intra-thread, ownership p = t + 128e
        int sig = 1 << (ls - 7);
        int eL  = ((j >> (ls - 7)) << (ls - 7 + 1)) | (j & (sig - 1));
        int pL  = t + 128 * eL;
        int q   = ((pL >> (ls + 1)) << ls) | (pL & (s - 1));
        o = make_float4(st[q*4+0], st[q*4+1], st[q*4+2], st[q*4+3]);
    }
    g_twp[id] = o;
}

// ---------------- main kernel ----------------
// Block = 128 threads = one row-group of 8 rows (4 packed row-pairs).
// Thread t: phase A/B ownership p = 8t+e (e=0..7), phase C ownership p = t+128e.
__global__ void __launch_bounds__(128) butterfly_main(
    const float* __restrict__ x,
    const float* __restrict__ bias,
    float* __restrict__ out)
{
    __shared__ float2 buf[4][1152];   // 1024 slots + 1/8 padding per row-pair
    const int t = threadIdx.x;
    const int rowbase = blockIdx.x * 8;

    // ---- input staging: coalesced LDG.128, interleave row pairs into shared ----
    #pragma unroll
    for (int c = 0; c < 4; c++) {
        const float4* r0 = reinterpret_cast<const float4*>(x + (size_t)(rowbase + 2*c    ) * 1024);
        const float4* r1 = reinterpret_cast<const float4*>(x + (size_t)(rowbase + 2*c + 1) * 1024);
        #pragma unroll
        for (int h = 0; h < 2; h++) {
            int f = t + 128 * h;
            float4 a = __ldcs(r0 + f);
            float4 b = __ldcs(r1 + f);
            int p0 = 4 * f;
            buf[c][(p0+0) + ((p0+0) >> 3)] = make_float2(a.x, b.x);
            buf[c][(p0+1) + ((p0+1) >> 3)] = make_float2(a.y, b.y);
            buf[c][(p0+2) + ((p0+2) >> 3)] = make_float2(a.z, b.z);
            buf[c][(p0+3) + ((p0+3) >> 3)] = make_float2(a.w, b.w);
        }
    }
    __syncthreads();

    ull D[4][8];
    #pragma unroll
    for (int c = 0; c < 4; c++)
        #pragma unroll
        for (int e = 0; e < 8; e++) {
            int p = 8 * t + e;
            float2 v = buf[c][p + (p >> 3)];
            D[c][e] = pk2(v.x, v.y);
        }

    const float4* TW = g_twp;

    // ---- phase A: strides 1,2,4 (intra-thread) ----
    #pragma unroll
    for (int ls = 0; ls < 3; ls++) {
        const int s = 1 << ls;
        #pragma unroll
        for (int j = 0; j < 4; j++) {
            float4 w = TW[(ls * 4 + j) * 128 + t];
            const int eL = ((j >> ls) << (ls + 1)) | (j & (s - 1));
            const int eH = eL + s;
            ull t00 = bc2(w.x), t01 = bc2(w.y), t10 = bc2(w.z), t11 = bc2(w.w);
            #pragma unroll
            for (int c = 0; c < 4; c++) {
                ull x0 = D[c][eL], x1 = D[c][eH];
                D[c][eL] = fma2(t00, x0, mul2(t01, x1));
                D[c][eH] = fma2(t10, x0, mul2(t11, x1));
            }
        }
    }

    // ---- phase B: strides 8,16,32,64 via warp shuffles (lane xor 1,2,4,8) ----
    #pragma unroll
    for (int ls = 3; ls < 7; ls++) {
        const int k = 1 << (ls - 3);
        #pragma unroll
        for (int j = 0; j < 4; j++) {
            float4 w = TW[(ls * 4 + j) * 128 + t];
            ull ta0 = bc2(w.x), tb0 = bc2(w.y), ta1 = bc2(w.z), tb1 = bc2(w.w);
            const int e0 = 2 * j, e1 = 2 * j + 1;
            #pragma unroll
            for (int c = 0; c < 4; c++) {
                ull o0 = __shfl_xor_sync(0xffffffffu, D[c][e0], k);
                D[c][e0] = fma2(ta0, D[c][e0], mul2(tb0, o0));
                ull o1 = __shfl_xor_sync(0xffffffffu, D[c][e1], k);
                D[c][e1] = fma2(ta1, D[c][e1], mul2(tb1, o1));
            }
        }
    }

    // ---- ownership transpose through shared: p = 8t+e  ->  p = t+128e ----
    __syncthreads();
    #pragma unroll
    for (int c = 0; c < 4; c++)
        #pragma unroll
        for (int e = 0; e < 8; e++) {
            int p = 8 * t + e;
            buf[c][p + (p >> 3)] = up2(D[c][e]);
        }
    __syncthreads();
    #pragma unroll
    for (int c = 0; c < 4; c++)
        #pragma unroll
        for (int e = 0; e < 8; e++) {
            int p = t + 128 * e;
            float2 v = buf[c][p + (p >> 3)];
            D[c][e] = pk2(v.x, v.y);
        }

    // ---- phase C: strides 128,256,512 (intra-thread in e) ----
    #pragma unroll
    for (int ls = 7; ls < 10; ls++) {
        const int sig = 1 << (ls - 7);
        #pragma unroll
        for (int j = 0; j < 4; j++) {
            float4 w = TW[(ls * 4 + j) * 128 + t];
            const int eL = ((j >> (ls - 7)) << (ls - 7 + 1)) | (j & (sig - 1));
            const int eH = eL + sig;
            ull t00 = bc2(w.x), t01 = bc2(w.y), t10 = bc2(w.z), t11 = bc2(w.w);
            #pragma unroll
            for (int c = 0; c < 4; c++) {
                ull x0 = D[c][eL], x1 = D[c][eH];
                D[c][eL] = fma2(t00, x0, mul2(t01, x1));
                D[c][eH] = fma2(t10, x0, mul2(t11, x1));
            }
        }
    }

    // ---- epilogue: add bias, coalesced streaming stores ----
    float bv[8];
    #pragma unroll
    for (int e = 0; e < 8; e++) bv[e] = bias[t + 128 * e];

    #pragma unroll
    for (int c = 0; c < 4; c++) {
        float* o0 = out + (size_t)(rowbase + 2*c    ) * 1024;
        float* o1 = out + (size_t)(rowbase + 2*c + 1) * 1024;
        #pragma unroll
        for (int e = 0; e < 8; e++) {
            float2 v = up2(D[c][e]);
            int p = t + 128 * e;
            __stcs(o0 + p, v.x + bv[e]);
            __stcs(o1 + p, v.y + bv[e]);
        }
    }
}

extern "C" void kernel_launch(void* const* d_in, const int* in_sizes, int n_in,
                              void* d_out, int out_size) {
    const float* x    = (const float*)d_in[0];   // [32768, 1024]
    const float* tw   = (const float*)d_in[1];   // [1,1,10,512,2,2]
    const float* bias = (const float*)d_in[2];   // [1024]
    float* out = (float*)d_out;

    int batch = in_sizes[0] / 1024;
    // 10*4*128 = 5120 table entries  ->  40 blocks of 128 (R2 bug: was 10 blocks,
    // leaving stages 3..9 zero => output degenerated to bias only)
    butterfly_prep<<<40, 128>>>(tw);
    butterfly_main<<<batch / 8, 128>>>(x, bias, out);
}

// round 4
// speedup vs baseline: 1.1281x; 1.1281x over previous
#include <cuda_runtime.h>

typedef unsigned long long ull;

// Repacked twiddles: [stage 0..9][j 0..3][t 0..127] float4, 80KB total.
__device__ float4 g_twp[10 * 4 * 128];

// ---------------- packed f32x2 helpers (Blackwell) ----------------
__device__ __forceinline__ ull bc2(float f) {
    ull r; asm("mov.b64 %0, {%1, %1};" : "=l"(r) : "f"(f)); return r;
}
__device__ __forceinline__ ull pk2(float a, float b) {
    ull r; asm("mov.b64 %0, {%1, %2};" : "=l"(r) : "f"(a), "f"(b)); return r;
}
__device__ __forceinline__ float2 up2(ull u) {
    float2 v; asm("mov.b64 {%0, %1}, %2;" : "=f"(v.x), "=f"(v.y) : "l"(u)); return v;
}
__device__ __forceinline__ ull mul2(ull a, ull b) {
    ull r; asm("mul.rn.f32x2 %0, %1, %2;" : "=l"(r) : "l"(a), "l"(b)); return r;
}
__device__ __forceinline__ ull fma2(ull a, ull b, ull c) {
    ull r; asm("fma.rn.f32x2 %0, %1, %2, %3;" : "=l"(r) : "l"(a), "l"(b), "l"(c)); return r;
}

// Optimal-padding physical index for the float2 transpose buffer.
// Store side p=8t+e: (p+(p>>4)) mod 16 distinct across 16 lanes -> 2-cycle (optimal for 64-bit).
// Read  side p=t+128e: conflict-free.
__device__ __forceinline__ int phys(int p) { return p + (p >> 4); }

// ---------------- twiddle repack kernel ----------------
// Original twiddle layout per stage: [512][2][2] floats (q, i, j).
// q for element pair (pL, pL+s): q = ((pL >> (ls+1)) << ls) | (pL & (s-1)).
__global__ void butterfly_prep(const float* __restrict__ tw) {
    int id = blockIdx.x * blockDim.x + threadIdx.x;   // 0..5119
    if (id >= 10 * 4 * 128) return;
    int t  = id & 127;
    int j  = (id >> 7) & 3;
    int ls = id >> 9;
    int s  = 1 << ls;
    const float* st = tw + ls * 2048;                 // stage base
    float4 o;
    if (ls < 3) {
        // phase A: intra-thread, ownership p = 8t + e
        int eL = ((j >> ls) << (ls + 1)) | (j & (s - 1));
        int pL = 8 * t + eL;
        int q  = ((pL >> (ls + 1)) << ls) | (pL & (s - 1));
        o = make_float4(st[q*4+0], st[q*4+1], st[q*4+2], st[q*4+3]);
    } else if (ls < 7) {
        // phase B: shfl stages; thread role i = bit (ls-3) of t
        int i = (t >> (ls - 3)) & 1;
        float v[4];
        #pragma unroll
        for (int m = 0; m < 2; m++) {
            int e = 2 * j + m;
            int p = 8 * t + e;
            int q = ((p >> (ls + 1)) << ls) | (p & (s - 1));
            if (i == 0) { v[2*m] = st[q*4+0]; v[2*m+1] = st[q*4+1]; }  // out = t00*own + t01*other
            else        { v[2*m] = st[q*4+3]; v[2*m+1] = st[q*4+2]; }  // out = t11*own + t10*other
        }
        o = make_float4(v[0], v[1], v[2], v[3]);
    } else {
        // phase C: intra-thread, ownership p = t + 128e
        int sig = 1 << (ls - 7);
        int eL  = ((j >> (ls - 7)) << (ls - 7 + 1)) | (j & (sig - 1));
        int pL  = t + 128 * eL;
        int q   = ((pL >> (ls + 1)) << ls) | (pL & (s - 1));
        o = make_float4(st[q*4+0], st[q*4+1], st[q*4+2], st[q*4+3]);
    }
    g_twp[id] = o;
}

// ---------------- main kernel ----------------
// Block = 128 threads = one row-group of 8 rows (4 packed row-pairs).
// Thread t: phase A/B ownership p = 8t+e (e=0..7), phase C ownership p = t+128e.
__global__ void __launch_bounds__(128) butterfly_main(
    const float* __restrict__ x,
    const float* __restrict__ bias,
    float* __restrict__ out)
{
    __shared__ float2 buf[4][1088];   // 1024 slots + 1/16 padding per row-pair
    const int t = threadIdx.x;
    const int rowbase = blockIdx.x * 8;

    // ---- input: DIRECT register load, no smem staging ----
    // Phase A ownership p = 8t+e is 32 contiguous bytes -> two LDG.128 per row.
    // Lane stride 32B: warp covers a contiguous 1KB; every sector fully used.
    ull D[4][8];
    #pragma unroll
    for (int c = 0; c < 4; c++) {
        const float4* r0 = reinterpret_cast<const float4*>(x + (size_t)(rowbase + 2*c    ) * 1024 + 8 * t);
        const float4* r1 = reinterpret_cast<const float4*>(x + (size_t)(rowbase + 2*c + 1) * 1024 + 8 * t);
        float4 a0 = __ldcs(r0);     float4 a1 = __ldcs(r0 + 1);
        float4 b0 = __ldcs(r1);     float4 b1 = __ldcs(r1 + 1);
        D[c][0] = pk2(a0.x, b0.x);  D[c][1] = pk2(a0.y, b0.y);
        D[c][2] = pk2(a0.z, b0.z);  D[c][3] = pk2(a0.w, b0.w);
        D[c][4] = pk2(a1.x, b1.x);  D[c][5] = pk2(a1.y, b1.y);
        D[c][6] = pk2(a1.z, b1.z);  D[c][7] = pk2(a1.w, b1.w);
    }

    const float4* TW = g_twp;

    // ---- phase A: strides 1,2,4 (intra-thread) ----
    #pragma unroll
    for (int ls = 0; ls < 3; ls++) {
        const int s = 1 << ls;
        #pragma unroll
        for (int j = 0; j < 4; j++) {
            float4 w = TW[(ls * 4 + j) * 128 + t];
            const int eL = ((j >> ls) << (ls + 1)) | (j & (s - 1));
            const int eH = eL + s;
            ull t00 = bc2(w.x), t01 = bc2(w.y), t10 = bc2(w.z), t11 = bc2(w.w);
            #pragma unroll
            for (int c = 0; c < 4; c++) {
                ull x0 = D[c][eL], x1 = D[c][eH];
                D[c][eL] = fma2(t00, x0, mul2(t01, x1));
                D[c][eH] = fma2(t10, x0, mul2(t11, x1));
            }
        }
    }

    // ---- phase B: strides 8,16,32,64 via warp shuffles (lane xor 1,2,4,8) ----
    #pragma unroll
    for (int ls = 3; ls < 7; ls++) {
        const int k = 1 << (ls - 3);
        #pragma unroll
        for (int j = 0; j < 4; j++) {
            float4 w = TW[(ls * 4 + j) * 128 + t];
            ull ta0 = bc2(w.x), tb0 = bc2(w.y), ta1 = bc2(w.z), tb1 = bc2(w.w);
            const int e0 = 2 * j, e1 = 2 * j + 1;
            #pragma unroll
            for (int c = 0; c < 4; c++) {
                ull o0 = __shfl_xor_sync(0xffffffffu, D[c][e0], k);
                D[c][e0] = fma2(ta0, D[c][e0], mul2(tb0, o0));
                ull o1 = __shfl_xor_sync(0xffffffffu, D[c][e1], k);
                D[c][e1] = fma2(ta1, D[c][e1], mul2(tb1, o1));
            }
        }
    }

    // ---- ownership transpose through shared: p = 8t+e  ->  p = t+128e ----
    #pragma unroll
    for (int c = 0; c < 4; c++)
        #pragma unroll
        for (int e = 0; e < 8; e++) {
            int p = 8 * t + e;
            buf[c][phys(p)] = up2(D[c][e]);
        }
    __syncthreads();
    #pragma unroll
    for (int c = 0; c < 4; c++)
        #pragma unroll
        for (int e = 0; e < 8; e++) {
            int p = t + 128 * e;
            float2 v = buf[c][phys(p)];
            D[c][e] = pk2(v.x, v.y);
        }

    // ---- phase C: strides 128,256,512 (intra-thread in e) ----
    #pragma unroll
    for (int ls = 7; ls < 10; ls++) {
        const int sig = 1 << (ls - 7);
        #pragma unroll
        for (int j = 0; j < 4; j++) {
            float4 w = TW[(ls * 4 + j) * 128 + t];
            const int eL = ((j >> (ls - 7)) << (ls - 7 + 1)) | (j & (sig - 1));
            const int eH = eL + sig;
            ull t00 = bc2(w.x), t01 = bc2(w.y), t10 = bc2(w.z), t11 = bc2(w.w);
            #pragma unroll
            for (int c = 0; c < 4; c++) {
                ull x0 = D[c][eL], x1 = D[c][eH];
                D[c][eL] = fma2(t00, x0, mul2(t01, x1));
                D[c][eH] = fma2(t10, x0, mul2(t11, x1));
            }
        }
    }

    // ---- epilogue: add bias, coalesced streaming stores ----
    float bv[8];
    #pragma unroll
    for (int e = 0; e < 8; e++) bv[e] = bias[t + 128 * e];

    #pragma unroll
    for (int c = 0; c < 4; c++) {
        float* o0 = out + (size_t)(rowbase + 2*c    ) * 1024;
        float* o1 = out + (size_t)(rowbase + 2*c + 1) * 1024;
        #pragma unroll
        for (int e = 0; e < 8; e++) {
            float2 v = up2(D[c][e]);
            int p = t + 128 * e;
            __stcs(o0 + p, v.x + bv[e]);
            __stcs(o1 + p, v.y + bv[e]);
        }
    }
}

extern "C" void kernel_launch(void* const* d_in, const int* in_sizes, int n_in,
                              void* d_out, int out_size) {
    const float* x    = (const float*)d_in[0];   // [32768, 1024]
    const float* tw   = (const float*)d_in[1];   // [1,1,10,512,2,2]
    const float* bias = (const float*)d_in[2];   // [1024]
    float* out = (float*)d_out;

    int batch = in_sizes[0] / 1024;
    butterfly_prep<<<40, 128>>>(tw);
    butterfly_main<<<batch / 8, 128>>>(x, bias, out);
}